// round 15
// baseline (speedup 1.0000x reference)
#include <cuda_runtime.h>
#include <cstdint>

// Table-batched embedding bag, SUM pooling.
// indices: int32 [T*B*L], offsets: int32 [T*B+1], weights: fp32 [T*E, 128],
// hash_size_cumsum: int32 [T+1], out: fp32 [B, T*128]
//
// Each warp owns 4 CONTIGUOUS bags; lane = one float4 (16B) of the 512B row.
// Continuous cross-bag cp.async pipeline: 3 banks x 4 slots, waves of 4 rows,
// steady-state wait_group 2 keeps 8 rows in flight through EVERY drain,
// including across bag boundaries (next bag's index load + first 2 waves are
// issued before the current bag's last 2 drains). Pipeline drains to zero
// only once per warp instead of once per bag -> removes per-bag startup
// bubble (dependent index-load chain with nothing in flight).

#define EMB_D    128
#define BAGS_PW  4            // bags per warp
#define WARPS_PB 4            // 128 threads/block; smem = 4*12*512B = 24KB

__global__ void __launch_bounds__(128, 8) tbe_fwd_kernel(
    const int*   __restrict__ indices,
    const int*   __restrict__ offsets,
    const float* __restrict__ weights,
    const int*   __restrict__ hsc,
    float*       __restrict__ out,
    int batch, int n_tables, int num_bags)
{
    // 4 warps * 12 slots (3 banks x 4) * 32 lanes * 16B = 24 KB
    __shared__ float4 buf[WARPS_PB * 12 * 32];

    const int lane = threadIdx.x & 31;
    const int wib  = (threadIdx.x >> 5);
    const int warp = blockIdx.x * WARPS_PB + wib;
    const int bag0 = warp * BAGS_PW;
    if (bag0 >= num_bags) return;
    const int nb = min(BAGS_PW, num_bags - bag0);

    float4* mybuf = buf + wib * (12 * 32) + lane;   // slot s at mybuf[s*32]
    const unsigned sbase = (unsigned)__cvta_generic_to_shared(mybuf);

    const float4* __restrict__ wv = reinterpret_cast<const float4*>(weights);

    // check all my bags have len 20 (CSR offsets strictly fixed-stride)
    const int off0 = offsets[bag0];
    bool uniform = true;
    #pragma unroll
    for (int j = 1; j <= BAGS_PW; j++)
        if (j <= nb) uniform &= (offsets[bag0 + j] == off0 + j * 20);

    float4 a0 = make_float4(0.f,0.f,0.f,0.f);
    float4 a1 = make_float4(0.f,0.f,0.f,0.f);
    float4 a2 = make_float4(0.f,0.f,0.f,0.f);
    float4 a3 = make_float4(0.f,0.f,0.f,0.f);

    // issue one wave of 4 rows from IDXREG at bag positions KOFF..KOFF+3
    // into bank ib (runtime), then advance ib mod 3
    #define ISSUE_WV(IDXREG, KOFF, BASE)                                       \
        do {                                                                   \
            const unsigned boff = sbase + ib * 2048u;                          \
            _Pragma("unroll")                                                  \
            for (int s = 0; s < 4; s++) {                                      \
                const unsigned row =                                           \
                    (unsigned)(__shfl_sync(0xffffffffu, IDXREG, (KOFF) + s) + (BASE)); \
                asm volatile("cp.async.cg.shared.global [%0], [%1], 16;\n"     \
                             :: "r"(boff + s * 512u),                          \
                                "l"(wv + (size_t)row * 32u + lane));           \
            }                                                                  \
            asm volatile("cp.async.commit_group;\n");                          \
            ib = (ib == 2) ? 0 : ib + 1;                                       \
        } while (0)

    #define DRAIN_WV()                                                         \
        do {                                                                   \
            const float4* d = mybuf + db * 128;                                \
            { const float4 v = d[0];  a0.x+=v.x; a0.y+=v.y; a0.z+=v.z; a0.w+=v.w; } \
            { const float4 v = d[32]; a1.x+=v.x; a1.y+=v.y; a1.z+=v.z; a1.w+=v.w; } \
            { const float4 v = d[64]; a2.x+=v.x; a2.y+=v.y; a2.z+=v.z; a2.w+=v.w; } \
            { const float4 v = d[96]; a3.x+=v.x; a3.y+=v.y; a3.z+=v.z; a3.w+=v.w; } \
            db = (db == 2) ? 0 : db + 1;                                       \
        } while (0)

    #define WAITG(N) asm volatile("cp.async.wait_group " #N ";\n" ::: "memory")

    if (uniform) {
        unsigned ib = 0, db = 0;
        int tbl_cur  = bag0 / batch;
        int base_cur = hsc[tbl_cur];
        int idx_cur  = (lane < 20) ? indices[off0 + lane] : 0;
        int idx_next = 0, base_next = 0;

        // prolog: first 2 waves of bag 0
        ISSUE_WV(idx_cur, 0, base_cur);
        ISSUE_WV(idx_cur, 4, base_cur);

        for (int i = 0; i < nb; i++) {
            const int bag = bag0 + i;

            ISSUE_WV(idx_cur, 8,  base_cur); WAITG(2); DRAIN_WV();
            ISSUE_WV(idx_cur, 12, base_cur); WAITG(2); DRAIN_WV();
            ISSUE_WV(idx_cur, 16, base_cur); WAITG(2); DRAIN_WV();

            if (i + 1 < nb) {
                // prefetch next bag while 2 waves still in flight
                idx_next  = (lane < 20) ? indices[off0 + (i + 1) * 20 + lane] : 0;
                const int tn = (bag + 1) / batch;
                base_next = hsc[tn];
                ISSUE_WV(idx_next, 0, base_next); WAITG(2);
            } else {
                WAITG(1);
            }
            DRAIN_WV();

            if (i + 1 < nb) { ISSUE_WV(idx_next, 4, base_next); WAITG(2); }
            else            { WAITG(0); }
            DRAIN_WV();

            // epilogue for bag i (overlaps next bag's in-flight loads)
            float4 acc;
            acc.x = (a0.x + a1.x) + (a2.x + a3.x);
            acc.y = (a0.y + a1.y) + (a2.y + a3.y);
            acc.z = (a0.z + a1.z) + (a2.z + a3.z);
            acc.w = (a0.w + a1.w) + (a2.w + a3.w);
            const int table = bag / batch;
            const int b     = bag - table * batch;
            float4* o = reinterpret_cast<float4*>(
                out + (size_t)b * ((size_t)n_tables * EMB_D) + (size_t)table * EMB_D);
            o[lane] = acc;
            a0 = make_float4(0.f,0.f,0.f,0.f);
            a1 = make_float4(0.f,0.f,0.f,0.f);
            a2 = make_float4(0.f,0.f,0.f,0.f);
            a3 = make_float4(0.f,0.f,0.f,0.f);

            idx_cur  = idx_next;
            base_cur = base_next;
        }
    } else {
        // generic fallback: per-bag flat issue-8 / wait / drain (banks 0..1)
        for (int i = 0; i < nb; i++) {
            const int seg   = bag0 + i;
            const int table = seg / batch;
            const int b     = seg - table * batch;
            const int base  = hsc[table];
            const int start = offsets[seg];
            const int end   = offsets[seg + 1];

            a0 = make_float4(0.f,0.f,0.f,0.f);
            a1 = make_float4(0.f,0.f,0.f,0.f);
            a2 = make_float4(0.f,0.f,0.f,0.f);
            a3 = make_float4(0.f,0.f,0.f,0.f);

            for (int chunk = start; chunk < end; chunk += 32) {
                const int cnt = min(32, end - chunk);
                const int myidx = (lane < cnt) ? indices[chunk + lane] : 0;

                for (int k = 0; k < cnt; k += 8) {
                    const int ns = min(8, cnt - k);
                    #pragma unroll
                    for (int s = 0; s < 8; s++) {
                        if (s < ns) {
                            const unsigned row =
                                (unsigned)(__shfl_sync(0xffffffffu, myidx, k + s) + base);
                            asm volatile("cp.async.cg.shared.global [%0], [%1], 16;\n"
                                         :: "r"(sbase + s * 512u),
                                            "l"(wv + (size_t)row * 32u + lane));
                        }
                    }
                    asm volatile("cp.async.commit_group;\n");
                    WAITG(0);
                    #pragma unroll
                    for (int s = 0; s < 8; s += 4) {
                        if (s < ns) { const float4 v = mybuf[s*32];
                            a0.x+=v.x; a0.y+=v.y; a0.z+=v.z; a0.w+=v.w; }
                        if (s+1 < ns) { const float4 v = mybuf[(s+1)*32];
                            a1.x+=v.x; a1.y+=v.y; a1.z+=v.z; a1.w+=v.w; }
                        if (s+2 < ns) { const float4 v = mybuf[(s+2)*32];
                            a2.x+=v.x; a2.y+=v.y; a2.z+=v.z; a2.w+=v.w; }
                        if (s+3 < ns) { const float4 v = mybuf[(s+3)*32];
                            a3.x+=v.x; a3.y+=v.y; a3.z+=v.z; a3.w+=v.w; }
                    }
                }
            }

            float4 acc;
            acc.x = (a0.x + a1.x) + (a2.x + a3.x);
            acc.y = (a0.y + a1.y) + (a2.y + a3.y);
            acc.z = (a0.z + a1.z) + (a2.z + a3.z);
            acc.w = (a0.w + a1.w) + (a2.w + a3.w);
            float4* o = reinterpret_cast<float4*>(
                out + (size_t)b * ((size_t)n_tables * EMB_D) + (size_t)table * EMB_D);
            o[lane] = acc;
        }
    }
    #undef ISSUE_WV
    #undef DRAIN_WV
    #undef WAITG
}

extern "C" void kernel_launch(void* const* d_in, const int* in_sizes, int n_in,
                              void* d_out, int out_size)
{
    const int*   indices = (const int*)d_in[0];
    const int*   offsets = (const int*)d_in[1];
    const float* weights = (const float*)d_in[2];
    const int*   hsc     = (const int*)d_in[3];
    float* out = (float*)d_out;

    const int num_bags = in_sizes[1] - 1;   // T*B
    const int n_tables = in_sizes[3] - 1;   // T
    const int batch    = num_bags / n_tables;

    const int warps  = (num_bags + BAGS_PW - 1) / BAGS_PW;
    const int blocks = (warps + WARPS_PB - 1) / WARPS_PB;

    tbe_fwd_kernel<<<blocks, WARPS_PB * 32>>>(
        indices, offsets, weights, hsc, out, batch, n_tables, num_bags);
}

// round 16
// speedup vs baseline: 1.0367x; 1.0367x over previous
#include <cuda_runtime.h>
#include <cstdint>

// Table-batched embedding bag, SUM pooling.
// indices: int32 [T*B*L], offsets: int32 [T*B+1], weights: fp32 [T*E, 128],
// hash_size_cumsum: int32 [T+1], out: fp32 [B, T*128]
//
// One warp per bag; lane = one float4 (16B) of the 512B row.
// cp.async.cg into per-warp smem staging (12 slots). Software-pipelined
// L=20 fast path: waves 8,4,8 with wait_group 1, so the warp always has
// >=4 rows in flight (R11 schedule, best measured: 5.98 TB/s).
// 192-thread blocks (6 warps, 36KB smem): 6 blocks/SM -> 36 warps/SM
// (56% occ cap vs R11's 50%); launch_bounds(192,6) -> regs<=56 (validated
// non-serializing in R12).

#define EMB_D    128
#define NSLOT    12           // staging slots per warp
#define WARPS_PB 6            // 192 threads/block; smem = 6*12*512B = 36KB

__global__ void __launch_bounds__(192, 6) tbe_fwd_kernel(
    const int*   __restrict__ indices,
    const int*   __restrict__ offsets,
    const float* __restrict__ weights,
    const int*   __restrict__ hsc,
    float*       __restrict__ out,
    int batch, int n_tables, int num_bags)
{
    // 6 warps * 12 slots * 32 lanes * 16B = 36 KB
    __shared__ float4 buf[WARPS_PB * NSLOT * 32];

    const int warp_global = (blockIdx.x * blockDim.x + threadIdx.x) >> 5;
    const int lane = threadIdx.x & 31;
    const int wib  = (threadIdx.x >> 5);
    if (warp_global >= num_bags) return;

    float4* mybuf = buf + wib * (NSLOT * 32) + lane;   // slot s at mybuf[s*32]
    const unsigned sbase = (unsigned)__cvta_generic_to_shared(mybuf);

    const int seg   = warp_global;
    const int table = seg / batch;
    const int b     = seg - table * batch;

    const int base  = hsc[table];          // T*E <= 4M, fits int32
    const int start = offsets[seg];
    const int end   = offsets[seg + 1];
    const int len   = end - start;

    const float4* __restrict__ wv = reinterpret_cast<const float4*>(weights);

    float4 a0 = make_float4(0.f, 0.f, 0.f, 0.f);
    float4 a1 = make_float4(0.f, 0.f, 0.f, 0.f);
    float4 a2 = make_float4(0.f, 0.f, 0.f, 0.f);
    float4 a3 = make_float4(0.f, 0.f, 0.f, 0.f);

    // issue CNT rows starting at bag pos KOFF into slots SLOT0..SLOT0+CNT-1
    #define ISSUE(KOFF, SLOT0, CNT)                                            \
        do {                                                                   \
            _Pragma("unroll")                                                  \
            for (int s = 0; s < (CNT); s++) {                                  \
                const unsigned row =                                           \
                    (unsigned)(__shfl_sync(0xffffffffu, myidx, (KOFF) + s) + base); \
                asm volatile("cp.async.cg.shared.global [%0], [%1], 16;\n"     \
                             :: "r"(sbase + ((SLOT0) + s) * 512u),             \
                                "l"(wv + (size_t)row * 32u + lane));           \
            }                                                                  \
            asm volatile("cp.async.commit_group;\n");                          \
        } while (0)

    #define DRAIN(SLOT0, CNT)                                                  \
        do {                                                                   \
            _Pragma("unroll")                                                  \
            for (int s = 0; s < (CNT); s += 4) {                               \
                { const float4 v = mybuf[((SLOT0)+s)*32];                      \
                  a0.x+=v.x; a0.y+=v.y; a0.z+=v.z; a0.w+=v.w; }               \
                if (s+1 < (CNT)) { const float4 v = mybuf[((SLOT0)+s+1)*32];   \
                  a1.x+=v.x; a1.y+=v.y; a1.z+=v.z; a1.w+=v.w; }               \
                if (s+2 < (CNT)) { const float4 v = mybuf[((SLOT0)+s+2)*32];   \
                  a2.x+=v.x; a2.y+=v.y; a2.z+=v.z; a2.w+=v.w; }               \
                if (s+3 < (CNT)) { const float4 v = mybuf[((SLOT0)+s+3)*32];   \
                  a3.x+=v.x; a3.y+=v.y; a3.z+=v.z; a3.w+=v.w; }               \
            }                                                                  \
        } while (0)

    if (len == 20) {
        // fast path: single index load; pipelined waves 8,4,8 over 12 slots
        const int myidx = (lane < 20) ? indices[start + lane] : 0;
        ISSUE(0, 0, 8);                                     // w0 -> slots 0..7
        ISSUE(8, 8, 4);                                     // w1 -> slots 8..11
        asm volatile("cp.async.wait_group 1;\n" ::: "memory");  // w0 ready, w1 in flight
        DRAIN(0, 8);
        ISSUE(12, 0, 8);                                    // w2 -> slots 0..7
        asm volatile("cp.async.wait_group 1;\n" ::: "memory");  // w1 ready, w2 in flight
        DRAIN(8, 4);
        asm volatile("cp.async.wait_group 0;\n" ::: "memory");  // w2 ready
        DRAIN(0, 8);
    } else {
        // generic fallback: flat issue-8 / wait / drain per group
        for (int chunk = start; chunk < end; chunk += 32) {
            const int cnt = min(32, end - chunk);
            const int myidx = (lane < cnt) ? indices[chunk + lane] : 0;

            for (int k = 0; k < cnt; k += 8) {
                const int ns = min(8, cnt - k);
                #pragma unroll
                for (int s = 0; s < 8; s++) {
                    if (s < ns) {
                        const unsigned row =
                            (unsigned)(__shfl_sync(0xffffffffu, myidx, k + s) + base);
                        asm volatile("cp.async.cg.shared.global [%0], [%1], 16;\n"
                                     :: "r"(sbase + s * 512u),
                                        "l"(wv + (size_t)row * 32u + lane));
                    }
                }
                asm volatile("cp.async.commit_group;\n");
                asm volatile("cp.async.wait_group 0;\n" ::: "memory");
                #pragma unroll
                for (int s = 0; s < 8; s += 4) {
                    if (s < ns) { const float4 v = mybuf[s*32];
                        a0.x+=v.x; a0.y+=v.y; a0.z+=v.z; a0.w+=v.w; }
                    if (s+1 < ns) { const float4 v = mybuf[(s+1)*32];
                        a1.x+=v.x; a1.y+=v.y; a1.z+=v.z; a1.w+=v.w; }
                    if (s+2 < ns) { const float4 v = mybuf[(s+2)*32];
                        a2.x+=v.x; a2.y+=v.y; a2.z+=v.z; a2.w+=v.w; }
                    if (s+3 < ns) { const float4 v = mybuf[(s+3)*32];
                        a3.x+=v.x; a3.y+=v.y; a3.z+=v.z; a3.w+=v.w; }
                }
            }
        }
    }
    #undef ISSUE
    #undef DRAIN

    float4 acc;
    acc.x = (a0.x + a1.x) + (a2.x + a3.x);
    acc.y = (a0.y + a1.y) + (a2.y + a3.y);
    acc.z = (a0.z + a1.z) + (a2.z + a3.z);
    acc.w = (a0.w + a1.w) + (a2.w + a3.w);

    float4* o = reinterpret_cast<float4*>(
        out + (size_t)b * ((size_t)n_tables * EMB_D) + (size_t)table * EMB_D);
    o[lane] = acc;
}

extern "C" void kernel_launch(void* const* d_in, const int* in_sizes, int n_in,
                              void* d_out, int out_size)
{
    const int*   indices = (const int*)d_in[0];
    const int*   offsets = (const int*)d_in[1];
    const float* weights = (const float*)d_in[2];
    const int*   hsc     = (const int*)d_in[3];
    float* out = (float*)d_out;

    const int num_bags = in_sizes[1] - 1;   // T*B
    const int n_tables = in_sizes[3] - 1;   // T
    const int batch    = num_bags / n_tables;

    const int blocks = (num_bags + WARPS_PB - 1) / WARPS_PB;

    tbe_fwd_kernel<<<blocks, WARPS_PB * 32>>>(
        indices, offsets, weights, hsc, out, batch, n_tables, num_bags);
}